// round 1
// baseline (speedup 1.0000x reference)
#include <cuda_runtime.h>
#include <math.h>

#define BB 16
#define LL 2048
#define MM 32000
#define DD 512
#define DV 128              // DD/4 float4 per row
#define SM_SCALE 0.03125f   // 1/sqrt(2*D) = 1/32
#define G_INNER 256
#define NCHUNK 16           // m-chunks for weighted sum
#define CHUNK_M (LL / NCHUNK)   // 128

// ---------------- scratch (no allocations allowed) ----------------
__device__ __align__(16) float g_inv_ew[MM + 1];
__device__ __align__(16) float g_inv_pw[LL];
__device__ __align__(16) float g_logits[BB * LL];
__device__ __align__(16) float g_probs[BB * LL];
__device__ __align__(16) float g_sel_partial[BB * NCHUNK * DD];
__device__ __align__(16) float g_sel[BB * DD];
__device__ __align__(16) float g_lse_partial[G_INNER * BB * 2];

__device__ __forceinline__ float warp_sum(float v) {
#pragma unroll
    for (int o = 16; o; o >>= 1) v += __shfl_xor_sync(0xffffffffu, v, o);
    return v;
}

// ---------------- 1) row inverse norms for ew (M+1 rows) and pw (L rows) ----
__global__ void norms_kernel(const float* __restrict__ ew, const float* __restrict__ pw) {
    int w = (blockIdx.x * blockDim.x + threadIdx.x) >> 5;
    int lane = threadIdx.x & 31;
    if (w >= (MM + 1) + LL) return;
    const float4* src = (w <= MM)
        ? (const float4*)(ew + (size_t)w * DD)
        : (const float4*)(pw + (size_t)(w - (MM + 1)) * DD);
    float s = 0.f;
#pragma unroll
    for (int k = 0; k < 4; k++) {
        float4 v = __ldg(&src[lane + 32 * k]);
        s += v.x * v.x + v.y * v.y + v.z * v.z + v.w * v.w;
    }
    s = warp_sum(s);
    if (lane == 0) {
        float inv = 1.0f / fmaxf(sqrtf(s), 1.0f);
        if (w <= MM) g_inv_ew[w] = inv;
        else g_inv_pw[w - (MM + 1)] = inv;
    }
}

// ---------------- 2) attention logits for the selected row only -------------
// logit[b][m] = ( ew[M]·ew[x_in] * invM*inv_xin + pw[q]·pw[m] * invq*invm ) / 32
__global__ void logits_kernel(const int* __restrict__ x, const int* __restrict__ mask_idx,
                              const float* __restrict__ ew, const float* __restrict__ pw) {
    int w = (blockIdx.x * blockDim.x + threadIdx.x) >> 5;   // 0 .. B*L-1 (exact)
    int lane = threadIdx.x & 31;
    int b = w >> 11;
    int m = w & (LL - 1);
    int q = __ldg(&mask_idx[b]);
    int xin = (m == q) ? MM : __ldg(&x[b * LL + m]);
    const float4* eM = (const float4*)(ew + (size_t)MM * DD);
    const float4* er = (const float4*)(ew + (size_t)xin * DD);
    const float4* pq = (const float4*)(pw + (size_t)q * DD);
    const float4* pm = (const float4*)(pw + (size_t)m * DD);
    float s1 = 0.f, s2 = 0.f;
#pragma unroll
    for (int k = 0; k < 4; k++) {
        float4 a = __ldg(&eM[lane + 32 * k]);
        float4 c = __ldg(&er[lane + 32 * k]);
        s1 += a.x * c.x + a.y * c.y + a.z * c.z + a.w * c.w;
        float4 u = __ldg(&pq[lane + 32 * k]);
        float4 v = __ldg(&pm[lane + 32 * k]);
        s2 += u.x * v.x + u.y * v.y + u.z * v.z + u.w * v.w;
    }
#pragma unroll
    for (int o = 16; o; o >>= 1) {
        s1 += __shfl_xor_sync(0xffffffffu, s1, o);
        s2 += __shfl_xor_sync(0xffffffffu, s2, o);
    }
    if (lane == 0) {
        float logit = s1 * g_inv_ew[MM] * g_inv_ew[xin]
                    + s2 * g_inv_pw[q] * g_inv_pw[m];
        g_logits[w] = logit * SM_SCALE;
    }
}

// ---------------- 3) softmax over L per batch -------------------------------
__global__ void softmax_kernel() {
    int b = blockIdx.x, t = threadIdx.x;
    __shared__ float sh[8];
    float v[8];
    float mx = -1e30f;
#pragma unroll
    for (int i = 0; i < 8; i++) {
        v[i] = g_logits[b * LL + i * 256 + t];
        mx = fmaxf(mx, v[i]);
    }
#pragma unroll
    for (int o = 16; o; o >>= 1) mx = fmaxf(mx, __shfl_xor_sync(0xffffffffu, mx, o));
    if ((t & 31) == 0) sh[t >> 5] = mx;
    __syncthreads();
    float bm = -1e30f;
#pragma unroll
    for (int w = 0; w < 8; w++) bm = fmaxf(bm, sh[w]);
    __syncthreads();
    float sum = 0.f;
#pragma unroll
    for (int i = 0; i < 8; i++) { v[i] = __expf(v[i] - bm); sum += v[i]; }
    sum = warp_sum(sum);
    if ((t & 31) == 0) sh[t >> 5] = sum;
    __syncthreads();
    float bs = 0.f;
#pragma unroll
    for (int w = 0; w < 8; w++) bs += sh[w];
    float inv = 1.0f / bs;
#pragma unroll
    for (int i = 0; i < 8; i++) g_probs[b * LL + i * 256 + t] = v[i] * inv;
}

// ---------------- 4) sel_output partials: sum_m p[m] * ew_renorm[row][d] ----
__global__ void __launch_bounds__(512) wsum_kernel(const int* __restrict__ x,
                                                   const int* __restrict__ mask_idx,
                                                   const float* __restrict__ ew) {
    int chunk = blockIdx.x, b = blockIdx.y, d = threadIdx.x;
    __shared__ float psc[CHUNK_M];
    __shared__ int rows[CHUNK_M];
    if (d < CHUNK_M) {
        int m = chunk * CHUNK_M + d;
        int q = __ldg(&mask_idx[b]);
        int r = (m == q) ? MM : __ldg(&x[b * LL + m]);
        rows[d] = r;
        psc[d] = g_probs[b * LL + m] * g_inv_ew[r];
    }
    __syncthreads();
    float acc = 0.f;
#pragma unroll 4
    for (int i = 0; i < CHUNK_M; i++)
        acc += psc[i] * __ldg(ew + (size_t)rows[i] * DD + d);
    g_sel_partial[((size_t)b * NCHUNK + chunk) * DD + d] = acc;
}

__global__ void __launch_bounds__(512) reduce_sel_kernel(float* out_sel) {
    int b = blockIdx.x, d = threadIdx.x;
    float acc = 0.f;
#pragma unroll
    for (int c = 0; c < NCHUNK; c++)
        acc += g_sel_partial[((size_t)b * NCHUNK + c) * DD + d];
    g_sel[b * DD + d] = acc;
    if (out_sel) out_sel[b * DD + d] = acc;
}

// ---------------- 5) inner products [32000 x 16] + fused online logsumexp ---
// warp processes 4 rows x 16 batches per group; register-exchange tree reduce.
__global__ void __launch_bounds__(256) inner_kernel(const float* __restrict__ ew) {
    __shared__ float4 sel_sh[BB * DV];    // 32 KB
    __shared__ float sh_m[8][16];
    __shared__ float sh_s[8][16];
    int tid = threadIdx.x;
    const float4* gsel = (const float4*)g_sel;
#pragma unroll
    for (int i = 0; i < 8; i++) sel_sh[tid + i * 256] = gsel[tid + i * 256];
    __syncthreads();

    int warp = tid >> 5, lane = tid & 31;
    int wg = blockIdx.x * 8 + warp;
    const int W = G_INNER * 8;

    // running lse per lane: slot A -> batch lane>>2, slot B -> batch 8+(lane>>2)
    float mA = -1e30f, sA = 0.f, mB = -1e30f, sB = 0.f;

    for (int g = wg; g < (MM / 4); g += W) {
        int row0 = g * 4;
        float4 ev[4][4];
#pragma unroll
        for (int r = 0; r < 4; r++) {
            const float4* rp = (const float4*)(ew + (size_t)(row0 + r) * DD);
#pragma unroll
            for (int v = 0; v < 4; v++) ev[r][v] = __ldg(&rp[lane + 32 * v]);
        }
        float myinv = __ldg(&g_inv_ew[row0 + (lane & 3)]);
#pragma unroll
        for (int p = 0; p < 2; p++) {
            float acc[32];
#pragma unroll
            for (int k = 0; k < 32; k++) acc[k] = 0.f;
#pragma unroll
            for (int bl = 0; bl < 8; bl++) {
                int b = p * 8 + bl;
#pragma unroll
                for (int v = 0; v < 4; v++) {
                    float4 s4 = sel_sh[b * DV + lane + 32 * v];
#pragma unroll
                    for (int r = 0; r < 4; r++) {
                        acc[bl * 4 + r] += ev[r][v].x * s4.x + ev[r][v].y * s4.y
                                         + ev[r][v].z * s4.z + ev[r][v].w * s4.w;
                    }
                }
            }
            // register-exchange tree reduce: lane j ends with total for index j
#pragma unroll
            for (int i = 0; i < 16; i++) {
                float lo = acc[i], hi = acc[i + 16];
                float send = (lane & 16) ? lo : hi;
                float recv = __shfl_xor_sync(0xffffffffu, send, 16);
                acc[i] = ((lane & 16) ? hi : lo) + recv;
            }
#pragma unroll
            for (int i = 0; i < 8; i++) {
                float lo = acc[i], hi = acc[i + 8];
                float send = (lane & 8) ? lo : hi;
                float recv = __shfl_xor_sync(0xffffffffu, send, 8);
                acc[i] = ((lane & 8) ? hi : lo) + recv;
            }
#pragma unroll
            for (int i = 0; i < 4; i++) {
                float lo = acc[i], hi = acc[i + 4];
                float send = (lane & 4) ? lo : hi;
                float recv = __shfl_xor_sync(0xffffffffu, send, 4);
                acc[i] = ((lane & 4) ? hi : lo) + recv;
            }
#pragma unroll
            for (int i = 0; i < 2; i++) {
                float lo = acc[i], hi = acc[i + 2];
                float send = (lane & 2) ? lo : hi;
                float recv = __shfl_xor_sync(0xffffffffu, send, 2);
                acc[i] = ((lane & 2) ? hi : lo) + recv;
            }
            {
                float lo = acc[0], hi = acc[1];
                float send = (lane & 1) ? lo : hi;
                float recv = __shfl_xor_sync(0xffffffffu, send, 1);
                acc[0] = ((lane & 1) ? hi : lo) + recv;
            }
            float val = acc[0] * myinv;  // dot for batch p*8+(lane>>2), row row0+(lane&3)
            if (p == 0) {
                if (val > mA) { sA = sA * __expf(mA - val) + 1.0f; mA = val; }
                else          { sA += __expf(val - mA); }
            } else {
                if (val > mB) { sB = sB * __expf(mB - val) + 1.0f; mB = val; }
                else          { sB += __expf(val - mB); }
            }
        }
    }
    // merge the 4 lanes that share a batch (xor 1, then 2)
#pragma unroll
    for (int o = 1; o <= 2; o <<= 1) {
        float m2 = __shfl_xor_sync(0xffffffffu, mA, o);
        float s2 = __shfl_xor_sync(0xffffffffu, sA, o);
        float mn = fmaxf(mA, m2);
        sA = sA * __expf(mA - mn) + s2 * __expf(m2 - mn);
        mA = mn;
        m2 = __shfl_xor_sync(0xffffffffu, mB, o);
        s2 = __shfl_xor_sync(0xffffffffu, sB, o);
        mn = fmaxf(mB, m2);
        sB = sB * __expf(mB - mn) + s2 * __expf(m2 - mn);
        mB = mn;
    }
    if ((lane & 3) == 0) {
        int bA = lane >> 2;
        sh_m[warp][bA] = mA;     sh_s[warp][bA] = sA;
        sh_m[warp][8 + bA] = mB; sh_s[warp][8 + bA] = sB;
    }
    __syncthreads();
    if (tid < 16) {
        float m = -1e30f, s = 0.f;
#pragma unroll
        for (int w2 = 0; w2 < 8; w2++) {
            float m2 = sh_m[w2][tid], s2 = sh_s[w2][tid];
            float mn = fmaxf(m, m2);
            s = s * __expf(m - mn) + s2 * __expf(m2 - mn);
            m = mn;
        }
        g_lse_partial[(blockIdx.x * 16 + tid) * 2 + 0] = m;
        g_lse_partial[(blockIdx.x * 16 + tid) * 2 + 1] = s;
    }
}

// ---------------- 6) finalize: lse merge + target dot + loss ----------------
__global__ void __launch_bounds__(512) finalize_kernel(const int* __restrict__ x,
                                                       const int* __restrict__ mask_idx,
                                                       const float* __restrict__ ew,
                                                       float* out_loss) {
    __shared__ float contrib[BB];
    int warp = threadIdx.x >> 5, lane = threadIdx.x & 31;
    int b = warp;
    float m = -1e30f, s = 0.f;
    for (int i = lane; i < G_INNER; i += 32) {
        float m2 = g_lse_partial[(i * 16 + b) * 2 + 0];
        float s2 = g_lse_partial[(i * 16 + b) * 2 + 1];
        float mn = fmaxf(m, m2);
        s = s * __expf(m - mn) + s2 * __expf(m2 - mn);
        m = mn;
    }
#pragma unroll
    for (int o = 16; o; o >>= 1) {
        float m2 = __shfl_xor_sync(0xffffffffu, m, o);
        float s2 = __shfl_xor_sync(0xffffffffu, s, o);
        float mn = fmaxf(m, m2);
        s = s * __expf(m - mn) + s2 * __expf(m2 - mn);
        m = mn;
    }
    int q = __ldg(&mask_idx[b]);
    int t = __ldg(&x[b * LL + q]);
    const float4* tr = (const float4*)(ew + (size_t)t * DD);
    const float4* sv = (const float4*)(g_sel + (size_t)b * DD);
    float dp = 0.f;
#pragma unroll
    for (int v = 0; v < 4; v++) {
        float4 a = __ldg(&tr[lane + 32 * v]);
        float4 c = sv[lane + 32 * v];
        dp += a.x * c.x + a.y * c.y + a.z * c.z + a.w * c.w;
    }
    dp = warp_sum(dp);
    if (lane == 0) contrib[b] = dp * g_inv_ew[t] - (m + logf(s));
    __syncthreads();
    if (threadIdx.x == 0 && out_loss) {
        float acc = 0.f;
#pragma unroll
        for (int b2 = 0; b2 < BB; b2++) acc += contrib[b2];
        *out_loss = -acc * (1.0f / BB);
    }
}

// ---------------- launch -----------------------------------------------------
extern "C" void kernel_launch(void* const* d_in, const int* in_sizes, int n_in,
                              void* d_out, int out_size) {
    const int* x = (const int*)d_in[0];
    const int* mask_idx = (const int*)d_in[1];
    const float* ew = (const float*)d_in[2];
    const float* pw = (const float*)d_in[3];
    float* out = (float*)d_out;

    float* out_loss;
    float* out_sel;
    if (out_size == BB * DD) { out_sel = out; out_loss = nullptr; }
    else if (out_size == 1)  { out_sel = nullptr; out_loss = out; }
    else                     { out_loss = out; out_sel = out + 1; }

    int nrows = (MM + 1) + LL;
    norms_kernel<<<(nrows + 7) / 8, 256>>>(ew, pw);
    logits_kernel<<<(BB * LL) / 8, 256>>>(x, mask_idx, ew, pw);
    softmax_kernel<<<BB, 256>>>();
    wsum_kernel<<<dim3(NCHUNK, BB), 512>>>(x, mask_idx, ew);
    reduce_sel_kernel<<<BB, 512>>>(out_sel);
    inner_kernel<<<G_INNER, 256>>>(ew);
    finalize_kernel<<<1, 512>>>(x, mask_idx, ew, out_loss);
}